// round 15
// baseline (speedup 1.0000x reference)
#include <cuda_runtime.h>
#include <math.h>

#define T_ 256
#define N_ 64
#define C_ 4096
#define L_ 32
#define S_ 65           // 2*L+1
#define BLANK_ 0
#define LOG2E 1.4426950408889634f
#define LN2   0.6931471805599453f

#define TP_ (T_ + 16)
#define DEPTH 16

// Scratch, layout [n][t][s]: LINEAR probabilities of the 65 extended labels.
__device__ __align__(16) float g_p_ext[N_ * TP_ * S_ + 128];
__device__ float g_per_n[N_];
__device__ int   g_cnt[T_];      // rows completed per timestep (0..64)
__device__ unsigned g_blkdone;   // reset by last consumer block each run

__device__ __forceinline__ float ex2(float x) {
    float y; asm("ex2.approx.ftz.f32 %0, %1;" : "=f"(y) : "f"(x)); return y;
}
__device__ __forceinline__ float lg2(float x) {
    float y; asm("lg2.approx.ftz.f32 %0, %1;" : "=f"(y) : "f"(x)); return y;
}
__device__ __forceinline__ float ldcg_f(const float* p) {
    float v; asm volatile("ld.global.cg.f32 %0, [%1];" : "=f"(v) : "l"(p)); return v;
}
__device__ __forceinline__ int ldcg_i(const int* p) {
    int v; asm volatile("ld.global.cg.s32 %0, [%1];" : "=r"(v) : "l"(p)); return v;
}
__device__ __forceinline__ unsigned redux_max_u32(unsigned v) {
    unsigned r;
    asm volatile("redux.sync.max.u32 %0, %1, 0xffffffff;" : "=r"(r) : "r"(v));
    return r;
}

__device__ __forceinline__ bool skip_at(const int* __restrict__ targets, int n, int s) {
    if (s < S_ && (s & 1) && s >= 2) {
        int lab  = targets[n * L_ + (s >> 1)];
        int lab2 = targets[n * L_ + (s >> 1) - 1];
        return (lab != BLANK_) && (lab != lab2);
    }
    return false;
}

// ascending watermark: rows [0, wm) confirmed complete (cnt == N_)
__device__ __forceinline__ void ensure_asc(int& wm, int target, int lane) {
    if (wm > target) return;
    const unsigned FULL = 0xffffffffu;
    while (wm <= target) {
        int idx = wm + lane;
        int c = N_;
        if (idx < T_) c = ldcg_i(g_cnt + idx);
        unsigned mask = __ballot_sync(FULL, c >= N_);
        unsigned inv = ~mask;
        wm += inv ? (__ffs(inv) - 1) : 32;
    }
    __threadfence();   // acquire
}

// descending watermark: rows (255-wmb, 255] confirmed complete
__device__ __forceinline__ void ensure_desc(int& wmb, int target, int lane) {
    int need = T_ - target;            // wmb >= need  <=>  row `target` ready
    if (wmb >= need) return;
    const unsigned FULL = 0xffffffffu;
    while (wmb < need) {
        int idx = (T_ - 1) - (wmb + lane);
        int c = N_;
        if (idx >= 0) c = ldcg_i(g_cnt + idx);
        unsigned mask = __ballot_sync(FULL, c >= N_);
        unsigned inv = ~mask;
        wmb += inv ? (__ffs(inv) - 1) : 32;
    }
    __threadfence();   // acquire
}

// Kernel 1 (primary): logsumexp + gather, one (t,n) row per block. Rows are
// produced from BOTH ends of t (even bid ascending, odd bid descending) so
// both consumer directions are production-paced. Signals g_cnt[t] per row.
__global__ void __launch_bounds__(256) lse_gather_kernel(
    const float* __restrict__ preds, const int* __restrict__ targets)
{
#if __CUDA_ARCH__ >= 900
    cudaTriggerProgrammaticLaunchCompletion();   // let consumer start early
#endif
    const unsigned FULL = 0xffffffffu;
    const int bid = blockIdx.x;
    const int row = (bid & 1) ? (T_ * N_ - 1 - (bid >> 1)) : (bid >> 1);
    const int t   = row / N_;
    const int n   = row % N_;
    const float* __restrict__ p = preds + (size_t)row * C_;
    const int tid = threadIdx.x;

    float v[16];
    const float4* __restrict__ p4 = (const float4*)p;
    #pragma unroll
    for (int k = 0; k < 4; k++) {
        float4 f = __ldcs(p4 + tid + k * 256);     // streaming read
        v[k*4+0] = f.x; v[k*4+1] = f.y; v[k*4+2] = f.z; v[k*4+3] = f.w;
    }

    float m = v[0];
    #pragma unroll
    for (int i = 1; i < 16; i++) m = fmaxf(m, v[i]);
    #pragma unroll
    for (int o = 16; o > 0; o >>= 1) m = fmaxf(m, __shfl_xor_sync(FULL, m, o));
    __shared__ float sm[8];
    if ((tid & 31) == 0) sm[tid >> 5] = m;
    __syncthreads();
    float bm = sm[0];
    #pragma unroll
    for (int i = 1; i < 8; i++) bm = fmaxf(bm, sm[i]);
    __syncthreads();

    const float bmL = bm * LOG2E;
    float s = 0.0f;
    #pragma unroll
    for (int i = 0; i < 16; i++) s += ex2(fmaf(v[i], LOG2E, -bmL));
    #pragma unroll
    for (int o = 16; o > 0; o >>= 1) s += __shfl_xor_sync(FULL, s, o);
    if ((tid & 31) == 0) sm[tid >> 5] = s;
    __syncthreads();
    float bs = sm[0];
    #pragma unroll
    for (int i = 1; i < 8; i++) bs += sm[i];

    const float lse = bm + lg2(bs) * LN2;

    if (tid < S_) {
        int label = (tid & 1) ? targets[n * L_ + (tid >> 1)] : BLANK_;
        g_p_ext[(n * TP_ + t) * S_ + tid] = ex2((p[label] - lse) * LOG2E);
    }
    __syncthreads();
    if (tid == 0) {
        __threadfence();                 // publish row before signaling
        atomicAdd(&g_cnt[t], 1);
    }
}

// Kernel 2 (secondary, PDL): fwd/bwd split CTC recursion, one block per n.
// Warp 0 FORWARD (rows <=127, stream A), warp 1 BACKWARD (rows >=128,
// stream B). Loads gated by g_cnt watermarks; recursion math identical to
// the round-13 kernel (rel 1.4e-6).
__global__ void __launch_bounds__(64) ctc_forward_kernel(
    const int* __restrict__ targets,
    const int* __restrict__ pred_lengths,
    const int* __restrict__ target_lengths,
    float*     __restrict__ out)
{
    const unsigned FULL = 0xffffffffu;
    const int tid  = threadIdx.x;
    const int warp = tid >> 5;
    const int lane = tid & 31;
    const bool fwd = (warp == 0);
    const int n    = blockIdx.x;

    const int tl = target_lengths[n];
    const int pl = pred_lengths[n];
    const int Sv = 2 * tl + 1;
    const int s0 = 3 * lane;

    __shared__ float sA[96];
    __shared__ float sG[96];
    __shared__ int   sE[2];

    bool valid[3];
    #pragma unroll
    for (int j = 0; j < 3; j++) valid[j] = ((s0 + j) < S_) && ((s0 + j) < Sv);

    const float* __restrict__ pn = g_p_ext + n * (TP_ * S_);
    float a[3];
    int E = 0;
    float lp[DEPTH][3];

    if (fwd) {
        bool skip[3];
        #pragma unroll
        for (int j = 0; j < 3; j++) skip[j] = skip_at(targets, n, s0 + j);

        int wm = 0;
        ensure_asc(wm, 16, lane);        // rows 0..16 ready

        // alpha0
        {
            float p0 = ldcg_f(pn + 0), p1 = ldcg_f(pn + 1);
            #pragma unroll
            for (int j = 0; j < 3; j++) {
                int s = s0 + j;
                float a0 = 0.0f;
                if (s == 0) a0 = p0;
                if (s == 1 && tl > 0) a0 = p1;
                a[j] = valid[j] ? a0 : 0.0f;
            }
        }

        // preload rows 1..16
        #pragma unroll
        for (int j = 0; j < DEPTH; j++) {
            const float* r = pn + (1 + j) * S_ + s0;
            lp[j][0] = ldcg_f(r); lp[j][1] = ldcg_f(r + 1); lp[j][2] = ldcg_f(r + 2);
        }

        #pragma unroll 16
        for (int t = 1; t <= 128; t++) {
            const int u = (t - 1) & (DEPTH - 1);
            float l0 = lp[u][0], l1 = lp[u][1], l2 = lp[u][2];
            {
                // refill: row t+16, clamped to 127 (rows >127 are only ever
                // consumed by discarded steps, so value is irrelevant)
                int rowf = t + DEPTH; if (rowf > 127) rowf = 127;
                ensure_asc(wm, rowf, lane);
                const float* r = pn + rowf * S_ + s0;
                lp[u][0] = ldcg_f(r); lp[u][1] = ldcg_f(r + 1); lp[u][2] = ldcg_f(r + 2);
            }

            float nb1 = __shfl_up_sync(FULL, a[1], 1);   // state s0-2
            float nb2 = __shfl_up_sync(FULL, a[2], 1);   // state s0-1
            if (lane == 0) { nb1 = 0.0f; nb2 = 0.0f; }

            float c0 = a[0] + nb2  + (skip[0] ? nb1  : 0.0f);
            float c1 = a[1] + a[0] + (skip[1] ? nb2  : 0.0f);
            float c2 = a[2] + a[1] + (skip[2] ? a[0] : 0.0f);

            if (t < 128 && t < pl) {      // apply steps 1..127 only
                a[0] = valid[0] ? (c0 * l0) : 0.0f;
                a[1] = valid[1] ? (c1 * l1) : 0.0f;
                a[2] = valid[2] ? (c2 * l2) : 0.0f;
            }

            if ((t & 3) == 0) {
                float mx = fmaxf(fmaxf(a[0], a[1]), a[2]);
                unsigned mb = redux_max_u32(__float_as_uint(mx));
                if (mb >= 0x00800000u) {
                    int e = (int)(mb >> 23) - 127;
                    float sc = __uint_as_float((unsigned)(127 - e) << 23);
                    a[0] *= sc; a[1] *= sc; a[2] *= sc;
                    E += e;
                }
            }
        }
        sA[s0] = a[0]; sA[s0 + 1] = a[1]; sA[s0 + 2] = a[2];
        if (lane == 0) sE[0] = E;
    } else {
        bool sk2 = skip_at(targets, n, s0 + 2);
        bool sk3 = skip_at(targets, n, s0 + 3);
        bool sk4 = skip_at(targets, n, s0 + 4);

        int wmb = 0;
        ensure_desc(wmb, 240, lane);     // rows 255..240 ready

        // g init = endpoint indicator
        const int end = 2 * tl;
        #pragma unroll
        for (int j = 0; j < 3; j++) {
            int s = s0 + j;
            float g0 = 0.0f;
            if (s == end) g0 = 1.0f;
            if (tl > 0 && s == end - 1) g0 = 1.0f;
            a[j] = valid[j] ? g0 : 0.0f;
        }

        // preload rows 255..240
        #pragma unroll
        for (int j = 0; j < DEPTH; j++) {
            const float* r = pn + (255 - j) * S_ + s0;
            lp[j][0] = ldcg_f(r); lp[j][1] = ldcg_f(r + 1); lp[j][2] = ldcg_f(r + 2);
        }

        #pragma unroll 16
        for (int td = 0; td < 128; td++) {
            const int u = td & (DEPTH - 1);
            const int t = 255 - td;
            float l0 = lp[u][0], l1 = lp[u][1], l2 = lp[u][2];
            {
                // refill: row t-16, clamped to 128 (rows <128 only consumed
                // by steps that never run)
                int rowb = t - DEPTH; if (rowb < 128) rowb = 128;
                ensure_desc(wmb, rowb, lane);
                const float* r = pn + rowb * S_ + s0;
                lp[u][0] = ldcg_f(r); lp[u][1] = ldcg_f(r + 1); lp[u][2] = ldcg_f(r + 2);
            }

            float h0 = a[0] * l0;
            float h1 = a[1] * l1;
            float h2 = a[2] * l2;
            float hd0 = __shfl_down_sync(FULL, h0, 1);   // state s0+3
            float hd1 = __shfl_down_sync(FULL, h1, 1);   // state s0+4
            if (lane == 31) { hd0 = 0.0f; hd1 = 0.0f; }

            if (t < pl) {
                a[0] = valid[0] ? (h0 + h1  + (sk2 ? h2  : 0.0f)) : 0.0f;
                a[1] = valid[1] ? (h1 + h2  + (sk3 ? hd0 : 0.0f)) : 0.0f;
                a[2] = valid[2] ? (h2 + hd0 + (sk4 ? hd1 : 0.0f)) : 0.0f;
            }

            if ((td & 3) == 3) {
                float mx = fmaxf(fmaxf(a[0], a[1]), a[2]);
                unsigned mb = redux_max_u32(__float_as_uint(mx));
                if (mb >= 0x00800000u) {
                    int e = (int)(mb >> 23) - 127;
                    float sc = __uint_as_float((unsigned)(127 - e) << 23);
                    a[0] *= sc; a[1] *= sc; a[2] *= sc;
                    E += e;
                }
            }
        }
        sG[s0] = a[0]; sG[s0 + 1] = a[1]; sG[s0 + 2] = a[2];
        if (lane == 0) sE[1] = E;
    }

    __syncthreads();

    // combine (warp 0): P = <alpha_127, g_128> * 2^(Ef+Eb)
    if (fwd) {
        float dot = sA[s0]     * sG[s0]
                  + sA[s0 + 1] * sG[s0 + 1]
                  + sA[s0 + 2] * sG[s0 + 2];
        #pragma unroll
        for (int o = 16; o > 0; o >>= 1) dot += __shfl_xor_sync(FULL, dot, o);

        if (lane == 0) {
            float nll = -(logf(dot) + (float)(sE[0] + sE[1]) * LN2);
            if (!isfinite(nll) || nll >= 1e29f) nll = 0.0f;
            int denom = tl > 0 ? tl : 1;
            g_per_n[n] = nll / (float)denom;
        }
    }

    // last-block-done finalize + counter reset (non-blocking)
    __syncthreads();
    if (tid == 0) {
        __threadfence();
        unsigned old = atomicAdd(&g_blkdone, 1u);
        if (old == (unsigned)(gridDim.x - 1)) {
            __threadfence();
            float acc = 0.0f;
            #pragma unroll
            for (int i = 0; i < N_; i++) acc += ldcg_f(g_per_n + i);
            out[0] = acc / (float)N_;
            // all producers & consumers finished: reset signals for replay
            for (int i = 0; i < T_; i++) g_cnt[i] = 0;
            g_blkdone = 0u;
        }
    }
}

extern "C" void kernel_launch(void* const* d_in, const int* in_sizes, int n_in,
                              void* d_out, int out_size)
{
    const float* preds          = (const float*)d_in[0];
    const int*   targets        = (const int*)d_in[1];
    const int*   pred_lengths   = (const int*)d_in[2];
    const int*   target_lengths = (const int*)d_in[3];
    float* out = (float*)d_out;

    lse_gather_kernel<<<T_ * N_, 256>>>(preds, targets);

    // consumer: programmatic dependent launch (overlaps producer tail);
    // falls back to sequential semantics if PDL is not honored.
    cudaLaunchConfig_t cfg = {};
    cfg.gridDim  = dim3(N_, 1, 1);
    cfg.blockDim = dim3(64, 1, 1);
    cfg.dynamicSmemBytes = 0;
    cfg.stream = 0;
    cudaLaunchAttribute attrs[1];
    attrs[0].id = cudaLaunchAttributeProgrammaticStreamSerialization;
    attrs[0].val.programmaticStreamSerializationAllowed = 1;
    cfg.attrs = attrs;
    cfg.numAttrs = 1;
    cudaLaunchKernelEx(&cfg, ctc_forward_kernel,
                       targets, pred_lengths, target_lengths, out);
}